// round 7
// baseline (speedup 1.0000x reference)
#include <cuda_runtime.h>
#include <cuda_bf16.h>

// y[i,a,b] = sum_{kj,kh,l} w[i,kj,kh,l] * U[a+kj-1, kh, b, l]   (zero pad on a+kj-1)
// U[ap,kh,b,l] = T(ap,kh,(b-1)%14, l+128) + T(ap,kh,b,l)
// T(ap,kh,b',c) = (0 <= b'+kh-1 < 14) ? x[c, ap, (b'+kh-2) mod 14] : 0

#define U_ELEMS (14 * 3 * 14 * 128)     // 75264
#define W_ELEMS (256 * 1152)            // 294912
#define U_BLOCKS 294                     // 294*256 == 75264
#define W_BLOCKS 1152                    // 1152*256 == 294912

__device__ float g_U[U_ELEMS];          // [ap][kh][b][l]
__device__ float g_Wt[W_ELEMS];         // packed: [k/4][i=256][4]  (i-coalesced)

// Fused prep: blocks [0,294) build U; blocks [294,1446) transpose/pack w.
__global__ void prep_kernel(const float* __restrict__ x, const float* __restrict__ w) {
    if (blockIdx.x < U_BLOCKS) {
        int e = blockIdx.x * 256 + threadIdx.x;      // < 75264
        int l  = e & 127;
        int b  = (e >> 7) % 14;
        int kh = (e / (128 * 14)) % 3;
        int ap = e / (128 * 14 * 3);

        float val = 0.0f;
        int t = b + kh - 1;
        if (t >= 0 && t < 14) {
            int wsrc = t - 1; if (wsrc < 0) wsrc += 14;
            val += x[l * 196 + ap * 14 + wsrc];
        }
        int bm = b - 1; if (bm < 0) bm += 14;
        int t1 = bm + kh - 1;
        if (t1 >= 0 && t1 < 14) {
            int wsrc = t1 - 1; if (wsrc < 0) wsrc += 14;
            val += x[(l + 128) * 196 + ap * 14 + wsrc];
        }
        g_U[e] = val;
    } else {
        int e = (blockIdx.x - U_BLOCKS) * 256 + threadIdx.x;  // < 294912, coalesced read
        int i = e / 1152;
        int k = e - i * 1152;
        g_Wt[(k >> 2) * 1024 + i * 4 + (k & 3)] = w[e];
    }
}

// Grid (a=14, i-tile=8, b-half=2). Block 256 = 8 warps; lane = channel i0+lane.
// Split-K over warps (144 each). u_s[b][k] layout -> LDS.128 = 2 ready f32x2 pairs.
__global__ __launch_bounds__(256)
void gemm_kernel(float* __restrict__ y) {
    __shared__ float u_s[7 * 1152];      // [bb=7][k=1152]; reused as reduction buffer

    const int a   = blockIdx.x;          // 0..13
    const int i0  = blockIdx.y * 32;
    const int h0  = blockIdx.z;          // b-half: b = h0*7 + bb
    const int tid = threadIdx.x;

    // ---- stage u_s[bb][k]: 2016 float4 writes, conflict-free, coalesced reads ----
    float4* u4s = (float4*)u_s;
#pragma unroll
    for (int it = 0; it < 8; it++) {
        int idx = it * 256 + tid;                    // < 2048; valid < 2016
        if (idx < 2016) {
            int kj = idx / 672;
            int r  = idx - kj * 672;
            int kh = r / 224;
            int r2 = r - kh * 224;
            int bb = r2 >> 5;
            int l4 = r2 & 31;
            int ap = a - 1 + kj;
            float4 v = make_float4(0.f, 0.f, 0.f, 0.f);
            if (ap >= 0 && ap < 14)
                v = ((const float4*)g_U)[ap * 1344 + kh * 448 + (h0 * 7 + bb) * 32 + l4];
            u4s[bb * 288 + kj * 96 + kh * 32 + l4] = v;
        }
    }
    __syncthreads();

    const int warp = tid >> 5;
    const int lane = tid & 31;

    unsigned long long acc2[7];
#pragma unroll
    for (int bb = 0; bb < 7; bb++) acc2[bb] = 0ull;

    // w pairs: ulonglong2 load = w[i][4k'..4k'+3] as two f32x2 pairs, coalesced.
    const ulonglong2* wp = ((const ulonglong2*)g_Wt) + (warp * 36) * 256 + i0 + lane;
    const ulonglong2* up = ((const ulonglong2*)u_s) + warp * 36;

#pragma unroll 9
    for (int t = 0; t < 36; t++) {
        ulonglong2 wv = wp[t * 256];                 // LDG.128 (coalesced, L2-hit)
#pragma unroll
        for (int bb = 0; bb < 7; bb++) {
            ulonglong2 uv = up[bb * 288 + t];        // LDS.128 broadcast = 2 f32x2 pairs
            asm("fma.rn.f32x2 %0, %1, %2, %0;" : "+l"(acc2[bb]) : "l"(wv.x), "l"(uv.x));
            asm("fma.rn.f32x2 %0, %1, %2, %0;" : "+l"(acc2[bb]) : "l"(wv.y), "l"(uv.y));
        }
    }

    __syncthreads();                                 // u_s reusable as red buffer
    float* red = u_s;                                // [warp][bb=7][lane]
#pragma unroll
    for (int bb = 0; bb < 7; bb++) {
        float lo, hi;
        asm("mov.b64 {%0, %1}, %2;" : "=f"(lo), "=f"(hi) : "l"(acc2[bb]));
        red[(warp * 7 + bb) * 32 + lane] = lo + hi;
    }
    __syncthreads();

    if (tid < 7 * 32) {
        int bb = tid >> 5;
        int i  = tid & 31;
        float s = 0.f;
#pragma unroll
        for (int wq = 0; wq < 8; wq++) s += red[(wq * 7 + bb) * 32 + i];
        y[(i0 + i) * 196 + a * 14 + h0 * 7 + bb] = s;
    }
}

extern "C" void kernel_launch(void* const* d_in, const int* in_sizes, int n_in,
                              void* d_out, int out_size) {
    const float* x = (const float*)d_in[0];
    const float* w = (const float*)d_in[1];
    float* y = (float*)d_out;

    prep_kernel<<<U_BLOCKS + W_BLOCKS, 256>>>(x, w);
    gemm_kernel<<<dim3(14, 8, 2), 256>>>(y);
}

// round 8
// speedup vs baseline: 1.2718x; 1.2718x over previous
#include <cuda_runtime.h>
#include <cuda_bf16.h>

// y[i,a,b] = sum_{kj,kh,l} w[i,kj,kh,l] * U[a+kj-1, kh, b, l]   (zero pad on a+kj-1)
// U[ap,kh,b,l] = T(ap,kh,(b-1)%14, l+128) + T(ap,kh,b,l)
// T(ap,kh,b',c) = (0 <= b'+kh-1 < 14) ? x[c, ap, (b'+kh-2) mod 14] : 0

#define U_ELEMS (14 * 3 * 14 * 128)     // 75264
#define W_ELEMS (256 * 1152)            // 294912
#define U_BLOCKS 294                     // 294*256 == 75264
#define W_BLOCKS 1152                    // 1152*256 == 294912
#define GEMM_SMEM (16128 * 4)            // 64512 B: [9][14][128] floats

__device__ float g_U[U_ELEMS];          // [ap][kh][b][l]
__device__ float g_Wt[W_ELEMS];         // packed: [k/4][i=256][4]  (i-coalesced)

// Fused prep: blocks [0,294) build U; blocks [294,1446) transpose/pack w.
__global__ void prep_kernel(const float* __restrict__ x, const float* __restrict__ w) {
    if (blockIdx.x < U_BLOCKS) {
        int e = blockIdx.x * 256 + threadIdx.x;      // < 75264
        int l  = e & 127;
        int b  = (e >> 7) % 14;
        int kh = (e / (128 * 14)) % 3;
        int ap = e / (128 * 14 * 3);

        float val = 0.0f;
        int t = b + kh - 1;
        if (t >= 0 && t < 14) {
            int wsrc = t - 1; if (wsrc < 0) wsrc += 14;
            val += x[l * 196 + ap * 14 + wsrc];
        }
        int bm = b - 1; if (bm < 0) bm += 14;
        int t1 = bm + kh - 1;
        if (t1 >= 0 && t1 < 14) {
            int wsrc = t1 - 1; if (wsrc < 0) wsrc += 14;
            val += x[(l + 128) * 196 + ap * 14 + wsrc];
        }
        g_U[e] = val;
    } else {
        int e = (blockIdx.x - U_BLOCKS) * 256 + threadIdx.x;  // < 294912, coalesced read
        int i = e / 1152;
        int k = e - i * 1152;
        g_Wt[(k >> 2) * 1024 + i * 4 + (k & 3)] = w[e];
    }
}

// Grid (a=14, i-tile=8), 512 threads = 16 warps. lane = output channel (i0+lane).
// Full K=1152 split across 16 warps (72 k each). Coalesced LDG from packed g_Wt.
__global__ __launch_bounds__(512, 1)
void gemm_kernel(float* __restrict__ y) {
    extern __shared__ float u_s[];       // [kq=9][b=14][l=128] = 16128 floats; reused as red

    const int a   = blockIdx.x;          // 0..13
    const int i0  = blockIdx.y * 32;
    const int tid = threadIdx.x;

    // ---- stage U rows ap = a-1 .. a+1 (zero outside [0,14)) ----
    float4* u4s = (float4*)u_s;
#pragma unroll
    for (int it = 0; it < 8; it++) {
        int idx = it * 512 + tid;                    // < 4096; valid < 4032
        if (idx < 4032) {
            int kj  = idx / 1344;                    // 5376/4
            int rem = idx - kj * 1344;
            int ap  = a - 1 + kj;
            float4 v = make_float4(0.f, 0.f, 0.f, 0.f);
            if (ap >= 0 && ap < 14) v = ((const float4*)g_U)[ap * 1344 + rem];
            u4s[idx] = v;
        }
    }
    __syncthreads();

    const int warp = tid >> 5;           // 0..15
    const int lane = tid & 31;

    float acc[14];
#pragma unroll
    for (int b = 0; b < 14; b++) acc[b] = 0.f;

    // w: lane reads float4 {k..k+3} for row i0+lane; consecutive lanes contiguous.
    const float4* wp = ((const float4*)g_Wt) + (warp * 18) * 256 + i0 + lane;
    const float4* u4 = (const float4*)u_s;
    const int k0 = warp * 72;

#pragma unroll 4
    for (int t = 0; t < 18; t++) {
        float4 wv = wp[t * 256];                     // coalesced LDG.128 (4 lines/warp)
        int k  = k0 + t * 4;
        int ub = (k >> 7) * 448 + ((k & 127) >> 2);  // float4 idx into u_s, b=0
#pragma unroll
        for (int b = 0; b < 14; b++) {
            float4 uv = u4[ub + b * 32];             // warp-broadcast LDS
            acc[b] = fmaf(wv.x, uv.x, acc[b]);
            acc[b] = fmaf(wv.y, uv.y, acc[b]);
            acc[b] = fmaf(wv.z, uv.z, acc[b]);
            acc[b] = fmaf(wv.w, uv.w, acc[b]);
        }
    }

    __syncthreads();                                 // u_s now reusable as red buffer
    float* red = u_s;                                // [warp=16][b=14][lane=32] = 7168 floats
#pragma unroll
    for (int b = 0; b < 14; b++) red[(warp * 14 + b) * 32 + lane] = acc[b];
    __syncthreads();

    if (tid < 14 * 32) {
        int b = tid >> 5;
        int i = tid & 31;
        float s = 0.f;
#pragma unroll
        for (int wq = 0; wq < 16; wq++) s += red[(wq * 14 + b) * 32 + i];
        y[(i0 + i) * 196 + a * 14 + b] = s;
    }
}

extern "C" void kernel_launch(void* const* d_in, const int* in_sizes, int n_in,
                              void* d_out, int out_size) {
    const float* x = (const float*)d_in[0];
    const float* w = (const float*)d_in[1];
    float* y = (float*)d_out;

    cudaFuncSetAttribute(gemm_kernel,
                         cudaFuncAttributeMaxDynamicSharedMemorySize, GEMM_SMEM);

    prep_kernel<<<U_BLOCKS + W_BLOCKS, 256>>>(x, w);
    gemm_kernel<<<dim3(14, 8), 512, GEMM_SMEM>>>(y);
}